// round 13
// baseline (speedup 1.0000x reference)
#include <cuda_runtime.h>
#include <cuda_bf16.h>
#include <cstdint>

// Problem constants: T=512, B=1024, DK=128, H=256, NH=4
#define T_MAX 512
#define BSZ   1024
#define DKDIM 128
#define VDIM  512      // 2*H
#define NHEAD 4
#define OUTD  512      // 2*H
#define KIN   2048     // NH*2*H

#define KSPLIT 4
#define KQ (KIN / KSPLIT)   // 512

// ---------------- scratch ----------------
__device__ float g_w[(size_t)BSZ * NHEAD * T_MAX];            // 8MB weights
__device__ float g_res[(size_t)2 * BSZ * KIN];                // 16MB res halves
__device__ __nv_bfloat16 g_w_hi[(size_t)OUTD * KIN];          // 2MB
__device__ __nv_bfloat16 g_w_lo[(size_t)OUTD * KIN];          // 2MB
__device__ float g_part[(size_t)KSPLIT * BSZ * OUTD];         // 8MB

static __device__ __forceinline__ float4 ldcs4(const float4* p) {
    return __ldcs(p);
}
__device__ __forceinline__ uint32_t smem_to_u32(const void* smem_ptr) {
    uint32_t addr;
    asm("{ .reg .u64 tmp; cvta.to.shared.u64 tmp, %1; cvt.u32.u64 %0, tmp; }"
        : "=r"(addr) : "l"(smem_ptr));
    return addr;
}
__device__ __forceinline__ void ldm_x4(uint32_t r[4], uint32_t addr) {
    asm volatile("ldmatrix.sync.aligned.m8n8.x4.shared.b16 {%0,%1,%2,%3}, [%4];"
        : "=r"(r[0]), "=r"(r[1]), "=r"(r[2]), "=r"(r[3]) : "r"(addr));
}
__device__ __forceinline__ void mma16816(float c[4], const uint32_t a[4],
                                         const uint32_t b0, const uint32_t b1) {
    asm volatile(
        "mma.sync.aligned.m16n8k16.row.col.f32.bf16.bf16.f32 "
        "{%0,%1,%2,%3}, {%4,%5,%6,%7}, {%8,%9}, {%0,%1,%2,%3};"
        : "+f"(c[0]), "+f"(c[1]), "+f"(c[2]), "+f"(c[3])
        : "r"(a[0]), "r"(a[1]), "r"(a[2]), "r"(a[3]), "r"(b0), "r"(b1));
}

// ---------------------------------------------------------------------------
// Kernel A1a: raw scaled logits -> g_w[b][n][m]. grid (BSZ, 4), 256 thr.
// 4-slot unroll per warp: 16 independent 16B loads in flight per lane.
// ---------------------------------------------------------------------------
__global__ __launch_bounds__(256) void dnd_logits_kernel(
    const float* __restrict__ keys,   // [T][B][DK]
    const float* __restrict__ rpe,    // [T][B]
    const float* __restrict__ query,  // [B][NH][DK]
    const int*   __restrict__ min_step_p)
{
    __shared__ __align__(16) float sQ[NHEAD * DKDIM];

    const int b    = blockIdx.x;
    const int q    = blockIdx.y;
    const int tid  = threadIdx.x;
    const int warp = tid >> 5;
    const int lane = tid & 31;
    const int M    = min_step_p[0];
    const int ms   = (M * q) >> 2;
    const int me   = (M * (q + 1)) >> 2;

    for (int i = tid; i < NHEAD * DKDIM; i += 256)
        sQ[i] = query[(size_t)b * NHEAD * DKDIM + i];
    __syncthreads();

    const int h = lane >> 3;
    const int j = lane & 7;
    float4 q4[4];
    #pragma unroll
    for (int it = 0; it < 4; ++it)
        q4[it] = ((const float4*)sQ)[h * 32 + it * 8 + j];

    float* __restrict__ wrow = g_w + ((size_t)b * NHEAD + h) * T_MAX;

    const int span  = me - ms;
    const int mfull = ms + (span & ~31);
    for (int m = ms + warp; m < mfull; m += 32) {
        float4 l[4][4];
        #pragma unroll
        for (int u = 0; u < 4; ++u) {
            const float4* __restrict__ kr =
                (const float4*)(keys + ((size_t)(m + 8 * u) * BSZ + b) * DKDIM);
            #pragma unroll
            for (int it = 0; it < 4; ++it) l[u][it] = ldcs4(kr + it * 8 + j);
        }
        float p[4] = {};
        #pragma unroll
        for (int u = 0; u < 4; ++u) {
            #pragma unroll
            for (int it = 0; it < 4; ++it) {
                p[u] += l[u][it].x * q4[it].x + l[u][it].y * q4[it].y
                      + l[u][it].z * q4[it].z + l[u][it].w * q4[it].w;
            }
        }
        #pragma unroll
        for (int u = 0; u < 4; ++u) p[u] += __shfl_down_sync(0xffffffffu, p[u], 4);
        #pragma unroll
        for (int u = 0; u < 4; ++u) p[u] += __shfl_down_sync(0xffffffffu, p[u], 2);
        #pragma unroll
        for (int u = 0; u < 4; ++u) p[u] += __shfl_down_sync(0xffffffffu, p[u], 1);
        if (j == 0) {
            #pragma unroll
            for (int u = 0; u < 4; ++u)
                wrow[m + 8 * u] = p[u] * __ldg(&rpe[(size_t)(m + 8 * u) * BSZ + b]);
        }
    }
    for (int m = mfull + warp; m < me; m += 8) {
        const float4* __restrict__ krow =
            (const float4*)(keys + ((size_t)m * BSZ + b) * DKDIM);
        float p = 0.0f;
        #pragma unroll
        for (int it = 0; it < 4; ++it) {
            const float4 k4 = ldcs4(krow + it * 8 + j);
            p += k4.x * q4[it].x + k4.y * q4[it].y
               + k4.z * q4[it].z + k4.w * q4[it].w;
        }
        p += __shfl_down_sync(0xffffffffu, p, 4);
        p += __shfl_down_sync(0xffffffffu, p, 2);
        p += __shfl_down_sync(0xffffffffu, p, 1);
        if (j == 0)
            wrow[m] = p * __ldg(&rpe[(size_t)m * BSZ + b]);
    }
}

// ---------------------------------------------------------------------------
// Kernel A1b: in-place softmax over g_w. grid BSZ, 128 thr, warp per head.
// ---------------------------------------------------------------------------
__global__ __launch_bounds__(128) void dnd_softmax_kernel(
    const int* __restrict__ min_step_p)
{
    const int b    = blockIdx.x;
    const int warp = threadIdx.x >> 5;
    const int lane = threadIdx.x & 31;
    const int M    = min_step_p[0];

    float* __restrict__ row = g_w + ((size_t)b * NHEAD + warp) * T_MAX;

    float v[16];
    #pragma unroll
    for (int i = 0; i < 16; ++i) {
        const int m = lane + 32 * i;
        v[i] = (m < M) ? row[m] : -1e30f;
    }
    float mx = -1e30f;
    #pragma unroll
    for (int i = 0; i < 16; ++i) mx = fmaxf(mx, v[i]);
    #pragma unroll
    for (int off = 16; off > 0; off >>= 1)
        mx = fmaxf(mx, __shfl_xor_sync(0xffffffffu, mx, off));
    float s = 0.0f;
    #pragma unroll
    for (int i = 0; i < 16; ++i) {
        v[i] = __expf(v[i] - mx);
        s += v[i];
    }
    #pragma unroll
    for (int off = 16; off > 0; off >>= 1)
        s += __shfl_xor_sync(0xffffffffu, s, off);
    const float inv = 1.0f / s;
    #pragma unroll
    for (int i = 0; i < 16; ++i) {
        const int m = lane + 32 * i;
        if (m < M) row[m] = v[i] * inv;
    }
}

// ---------------------------------------------------------------------------
// Kernel A2: partial res over an m-half. grid (BSZ, 2), 128 threads.
// ---------------------------------------------------------------------------
__global__ __launch_bounds__(128) void dnd_apply_kernel(
    const float* __restrict__ vals,   // [T][B][VDIM]
    const int*   __restrict__ min_step_p)
{
    __shared__ __align__(16) float sW[NHEAD][T_MAX];

    const int b    = blockIdx.x;
    const int half = blockIdx.y;
    const int tid  = threadIdx.x;
    const int M    = min_step_p[0];
    const int ms   = (M * half) >> 1;
    const int me   = (M * (half + 1)) >> 1;

    {
        const float4* w4 = (const float4*)(g_w + (size_t)b * NHEAD * T_MAX);
        float4* s4 = (float4*)&sW[0][0];
        #pragma unroll
        for (int i = 0; i < 4; ++i)
            s4[tid + 128 * i] = w4[tid + 128 * i];
    }
    __syncthreads();

    float acc[NHEAD][4] = {};
    const float4* __restrict__ V4 = (const float4*)vals;
    const size_t rowstride = (size_t)BSZ * (VDIM / 4);
    const size_t base = (size_t)b * (VDIM / 4) + tid;

    const int span = me - ms;
    const int mend = ms + (span & ~7);
    for (int m0 = ms; m0 < mend; m0 += 8) {
        float4 v[8];
        #pragma unroll
        for (int u = 0; u < 8; ++u)
            v[u] = ldcs4(V4 + base + (size_t)(m0 + u) * rowstride);

        #pragma unroll
        for (int n = 0; n < NHEAD; ++n) {
            const float4 wa = *(const float4*)&sW[n][m0];
            const float4 wb = *(const float4*)&sW[n][m0 + 4];
            acc[n][0] += wa.x * v[0].x; acc[n][1] += wa.x * v[0].y;
            acc[n][2] += wa.x * v[0].z; acc[n][3] += wa.x * v[0].w;
            acc[n][0] += wa.y * v[1].x; acc[n][1] += wa.y * v[1].y;
            acc[n][2] += wa.y * v[1].z; acc[n][3] += wa.y * v[1].w;
            acc[n][0] += wa.z * v[2].x; acc[n][1] += wa.z * v[2].y;
            acc[n][2] += wa.z * v[2].z; acc[n][3] += wa.z * v[2].w;
            acc[n][0] += wa.w * v[3].x; acc[n][1] += wa.w * v[3].y;
            acc[n][2] += wa.w * v[3].z; acc[n][3] += wa.w * v[3].w;
            acc[n][0] += wb.x * v[4].x; acc[n][1] += wb.x * v[4].y;
            acc[n][2] += wb.x * v[4].z; acc[n][3] += wb.x * v[4].w;
            acc[n][0] += wb.y * v[5].x; acc[n][1] += wb.y * v[5].y;
            acc[n][2] += wb.y * v[5].z; acc[n][3] += wb.y * v[5].w;
            acc[n][0] += wb.z * v[6].x; acc[n][1] += wb.z * v[6].y;
            acc[n][2] += wb.z * v[6].z; acc[n][3] += wb.z * v[6].w;
            acc[n][0] += wb.w * v[7].x; acc[n][1] += wb.w * v[7].y;
            acc[n][2] += wb.w * v[7].z; acc[n][3] += wb.w * v[7].w;
        }
    }
    for (int m = mend; m < me; ++m) {
        const float4 v = ldcs4(V4 + base + (size_t)m * rowstride);
        #pragma unroll
        for (int n = 0; n < NHEAD; ++n) {
            const float w = sW[n][m];
            acc[n][0] += w * v.x; acc[n][1] += w * v.y;
            acc[n][2] += w * v.z; acc[n][3] += w * v.w;
        }
    }

    float* __restrict__ rdst = g_res + (size_t)half * BSZ * KIN;
    const int v0 = 4 * tid;
    #pragma unroll
    for (int n = 0; n < NHEAD; ++n) {
        float4 o;
        o.x = acc[n][0]; o.y = acc[n][1]; o.z = acc[n][2]; o.w = acc[n][3];
        *(float4*)&rdst[((size_t)b * NHEAD + n) * VDIM + v0] = o;
    }
}

// ---------------------------------------------------------------------------
// Conversion: W -> bf16 hi/lo (error-compensated split)
// ---------------------------------------------------------------------------
__global__ __launch_bounds__(256) void dnd_conv_w_kernel(
    const float* __restrict__ W)
{
    const size_t i = (size_t)blockIdx.x * 256 + threadIdx.x;   // float4 index
    const float4 a = ((const float4*)W)[i];
    float s[4] = {a.x, a.y, a.z, a.w};
    __nv_bfloat162 h01, h23, l01, l23;
    h01.x = __float2bfloat16(s[0]);
    h01.y = __float2bfloat16(s[1]);
    h23.x = __float2bfloat16(s[2]);
    h23.y = __float2bfloat16(s[3]);
    l01.x = __float2bfloat16(s[0] - __bfloat162float(h01.x));
    l01.y = __float2bfloat16(s[1] - __bfloat162float(h01.y));
    l23.x = __float2bfloat16(s[2] - __bfloat162float(h23.x));
    l23.y = __float2bfloat16(s[3] - __bfloat162float(h23.y));
    ((__nv_bfloat162*)g_w_hi)[2 * i]     = h01;
    ((__nv_bfloat162*)g_w_hi)[2 * i + 1] = h23;
    ((__nv_bfloat162*)g_w_lo)[2 * i]     = l01;
    ((__nv_bfloat162*)g_w_lo)[2 * i + 1] = l23;
}

// ---------------------------------------------------------------------------
// Kernel B: bf16 mma.sync GEMM with hi/lo compensation.
// A is read as fp32 (sum of the two res halves) and split hi/lo on the fly
// during the smem staging -> no separate res conversion pass.
// Tile M=128, N=64, BK=32, 256 threads (8 warps: 4 m x 2 n, warp = 32x32).
// grid (8, 8, KSPLIT) = 256 CTAs. Double-buffered padded smem.
// ---------------------------------------------------------------------------
#define TCM 128
#define TCN 64
#define TCBK 32
#define ASTRIDE 80           // bytes per smem row (32 bf16 + 8 pad)
#define STG 30720            // bytes per stage
#define OFF_AHI 0
#define OFF_ALO 10240
#define OFF_BHI 20480
#define OFF_BLO 25600
#define NSTAGE (KQ / TCBK)   // 16
#define SMEM_DYN (2 * STG)

__global__ __launch_bounds__(256, 1) void dnd_gemm_mma_kernel()
{
    extern __shared__ __align__(16) char smem[];
    const uint32_t sbase = smem_to_u32(smem);

    const int tid  = threadIdx.x;
    const int wid  = tid >> 5;
    const int lane = tid & 31;
    const int bx = blockIdx.x;   // N tile 0..7
    const int by = blockIdx.y;   // M tile 0..7
    const int kz = blockIdx.z;   // 0..KSPLIT-1
    const int wm = wid & 3;      // warp m 0..3 (32 rows each)
    const int wn = wid >> 2;     // warp n 0..1 (32 cols each)

    const size_t arow0 = (size_t)by * TCM;
    const size_t brow0 = (size_t)bx * TCN;
    const size_t kofs  = (size_t)kz * KQ;

    // A loader: 1024 float4 per 128x32 tile -> 4 per thread (fp32, x2 halves)
    const int ar = tid >> 1;            // rows 0..127, 2 threads per row
    const int ac = (tid & 1) * 4;       // float4 col 0..7 (4 per thread)
    const uint32_t sArow = ar * ASTRIDE;
    const float* gA0 = g_res + (arow0 + ar) * KIN + kofs + ac * 4;
    const float* gA1 = gA0 + (size_t)BSZ * KIN;
    // B loader: 256 uint4 per 64x32 bf16 tile -> 1 per thread per array
    const int br = tid >> 2;            // rows 0..63
    const int bj = tid & 3;             // uint4 col
    const uint32_t sBoff = br * ASTRIDE + bj * 16;
    const __nv_bfloat16* gBh = g_w_hi + (brow0 + br) * KIN + kofs + bj * 8;
    const __nv_bfloat16* gBl = g_w_lo + (brow0 + br) * KIN + kofs + bj * 8;

    float4 pA0[4], pA1[4];
    uint4 pBh, pBl;

    auto stage_store = [&](char* s) {
        #pragma unroll
        for (int i = 0; i < 4; ++i) {
            float v0 = pA0[i].x + pA1[i].x;
            float v1 = pA0[i].y + pA1[i].y;
            float v2 = pA0[i].z + pA1[i].z;
            float v3 = pA0[i].w + pA1[i].w;
            __nv_bfloat162 h01, h23, l01, l23;
            h01.x = __float2bfloat16(v0);
            h01.y = __float2bfloat16(v1);
            h23.x = __float2bfloat16(v2);
            h23.y = __float2bfloat16(v3);
            l01.x = __float2bfloat16(v0 - __bfloat162float(h01.x));
            l01.y = __float2bfloat16(v1 - __bfloat162float(h01.y));
            l23.x = __float2bfloat16(v2 - __bfloat162float(h23.x));
            l23.y = __float2bfloat16(v3 - __bfloat162float(h23.y));
            uint2 hh, ll;
            hh.x = *(uint32_t*)&h01; hh.y = *(uint32_t*)&h23;
            ll.x = *(uint32_t*)&l01; ll.y = *(uint32_t*)&l23;
            *(uint2*)(s + OFF_AHI + sArow + (ac + i) * 8) = hh;
            *(uint2*)(s + OFF_ALO + sArow + (ac + i) * 8) = ll;
        }
        *(uint4*)(s + OFF_BHI + sBoff) = pBh;
        *(uint4*)(s + OFF_BLO + sBoff) = pBl;
    };

    // stage 0 load
    #pragma unroll
    for (int i = 0; i < 4; ++i) {
        pA0[i] = *(const float4*)(gA0 + i * 4);
        pA1[i] = *(const float4*)(gA1 + i * 4);
    }
    pBh = *(const uint4*)gBh;
    pBl = *(const uint4*)gBl;
    stage_store(smem);
    __syncthreads();

    // ldmatrix per-lane offsets
    const int aRowOff = ((lane >> 3) & 1) * 8 + (lane & 7);
    const int aKOff   = ((lane >> 4) & 1) * 8;
    const int bNOff   = ((lane >> 4) & 1) * 8 + (lane & 7);
    const int bKOff   = ((lane >> 3) & 1) * 8;

    float acc[2][4][4] = {};

    for (int st = 0; st < NSTAGE; ++st) {
        const int buf = st & 1;
        const uint32_t bb = sbase + buf * STG;

        if (st + 1 < NSTAGE) {
            const int ke = (st + 1) * TCBK;
            #pragma unroll
            for (int i = 0; i < 4; ++i) {
                pA0[i] = *(const float4*)(gA0 + ke + i * 4);
                pA1[i] = *(const float4*)(gA1 + ke + i * 4);
            }
            pBh = *(const uint4*)(gBh + ke);
            pBl = *(const uint4*)(gBl + ke);
        }

        #pragma unroll
        for (int ks = 0; ks < TCBK; ks += 16) {
            uint32_t Ah[2][4], Al[2][4], Bh[2][4], Bl[2][4];
            #pragma unroll
            for (int i = 0; i < 2; ++i) {
                const uint32_t arow = (wm * 32 + i * 16 + aRowOff) * ASTRIDE
                                    + (ks + aKOff) * 2;
                ldm_x4(Ah[i], bb + OFF_AHI + arow);
                ldm_x4(Al[i], bb + OFF_ALO + arow);
            }
            #pragma unroll
            for (int t = 0; t < 2; ++t) {
                const uint32_t brow = (wn * 32 + t * 16 + bNOff) * ASTRIDE
                                    + (ks + bKOff) * 2;
                ldm_x4(Bh[t], bb + OFF_BHI + brow);
                ldm_x4(Bl[t], bb + OFF_BLO + brow);
            }
            #pragma unroll
            for (int i = 0; i < 2; ++i) {
                #pragma unroll
                for (int t = 0; t < 2; ++t) {
                    #pragma unroll
                    for (int u = 0; u < 2; ++u) {
                        const int jj = t * 2 + u;
                        mma16816(acc[i][jj], Ah[i], Bh[t][2*u], Bh[t][2*u+1]);
                        mma16816(acc[i][jj], Ah[i], Bl[t][2*u], Bl[t][2*u+1]);
                        mma16816(acc[i][jj], Al[i], Bh[t][2*u], Bh[t][2*u+1]);
                    }
                }
            }
        }

        if (st + 1 < NSTAGE) {
            stage_store(smem + ((st + 1) & 1) * STG);
        }
        __syncthreads();
    }

    // epilogue: c0,c1 at (row, col), c2,c3 at (row+8, col)
    float* __restrict__ part = g_part + (size_t)kz * BSZ * OUTD;
    const int rbase = by * TCM + wm * 32 + (lane >> 2);
    const int cbase = bx * TCN + wn * 32 + 2 * (lane & 3);
    #pragma unroll
    for (int i = 0; i < 2; ++i) {
        #pragma unroll
        for (int jj = 0; jj < 4; ++jj) {
            const int r = rbase + i * 16;
            const int c = cbase + jj * 8;
            float2 o0; o0.x = acc[i][jj][0]; o0.y = acc[i][jj][1];
            float2 o1; o1.x = acc[i][jj][2]; o1.y = acc[i][jj][3];
            *(float2*)(part + (size_t)r * OUTD + c) = o0;
            *(float2*)(part + (size_t)(r + 8) * OUTD + c) = o1;
        }
    }
}

// ---------------------------------------------------------------------------
// Kernel C: out = sum(part[0..KSPLIT-1]) + bias
// ---------------------------------------------------------------------------
__global__ __launch_bounds__(256) void dnd_reduce_kernel(
    const float* __restrict__ bias,
    float* __restrict__ out)
{
    const int i = blockIdx.x * 256 + threadIdx.x;
    const size_t stride4 = (size_t)BSZ * OUTD / 4;
    float4 o = ((const float4*)g_part)[i];
    #pragma unroll
    for (int p = 1; p < KSPLIT; ++p) {
        const float4 a = ((const float4*)g_part)[i + (size_t)p * stride4];
        o.x += a.x; o.y += a.y; o.z += a.z; o.w += a.w;
    }
    const float4 bz = ((const float4*)bias)[i & (OUTD / 4 - 1)];
    o.x += bz.x; o.y += bz.y; o.z += bz.z; o.w += bz.w;
    ((float4*)out)[i] = o;
}

// ---------------------------------------------------------------------------
// Launch
// ---------------------------------------------------------------------------
extern "C" void kernel_launch(void* const* d_in, const int* in_sizes, int n_in,
                              void* d_out, int out_size)
{
    const float* keys  = (const float*)d_in[0];
    const float* vals  = (const float*)d_in[1];
    const float* rpe   = (const float*)d_in[2];
    const float* query = (const float*)d_in[3];
    const float* W     = (const float*)d_in[4];
    const float* bias  = (const float*)d_in[5];
    const int*   mstep = (const int*)d_in[6];

    float* out = (float*)d_out;

    (void)cudaFuncSetAttribute(dnd_gemm_mma_kernel,
        cudaFuncAttributeMaxDynamicSharedMemorySize, SMEM_DYN);

    // W conversion is independent of everything else
    dnd_conv_w_kernel<<<(OUTD * KIN / 4) / 256, 256>>>(W);

    dim3 lgrid(BSZ, 4);
    dnd_logits_kernel<<<lgrid, 256>>>(keys, rpe, query, mstep);

    dnd_softmax_kernel<<<BSZ, 128>>>(mstep);

    dim3 agrid(BSZ, 2);
    dnd_apply_kernel<<<agrid, 128>>>(vals, mstep);

    dim3 ggrid(OUTD / TCN, BSZ / TCM, KSPLIT);   // (8, 8, 4)
    dnd_gemm_mma_kernel<<<ggrid, 256, SMEM_DYN>>>();

    dnd_reduce_kernel<<<(BSZ * OUTD / 4) / 256, 256>>>(bias, out);
}

// round 14
// speedup vs baseline: 1.1228x; 1.1228x over previous
#include <cuda_runtime.h>
#include <cuda_bf16.h>
#include <cstdint>

// Problem constants: T=512, B=1024, DK=128, H=256, NH=4
#define T_MAX 512
#define BSZ   1024
#define DKDIM 128
#define VDIM  512      // 2*H
#define NHEAD 4
#define OUTD  512      // 2*H
#define KIN   2048     // NH*2*H

#define KSPLIT 4
#define KQ (KIN / KSPLIT)   // 512

// ---------------- scratch ----------------
__device__ float g_w[(size_t)BSZ * NHEAD * T_MAX];            // 8MB raw logits
__device__ float g_res[(size_t)2 * BSZ * KIN];                // 16MB res halves
__device__ __nv_bfloat16 g_res_hi[(size_t)BSZ * KIN];         // 4MB
__device__ __nv_bfloat16 g_res_lo[(size_t)BSZ * KIN];         // 4MB
__device__ __nv_bfloat16 g_w_hi[(size_t)OUTD * KIN];          // 2MB
__device__ __nv_bfloat16 g_w_lo[(size_t)OUTD * KIN];          // 2MB
__device__ float g_part[(size_t)KSPLIT * BSZ * OUTD];         // 8MB

static __device__ __forceinline__ float4 ldcs4(const float4* p) {
    return __ldcs(p);
}
__device__ __forceinline__ uint32_t smem_to_u32(const void* smem_ptr) {
    uint32_t addr;
    asm("{ .reg .u64 tmp; cvta.to.shared.u64 tmp, %1; cvt.u32.u64 %0, tmp; }"
        : "=r"(addr) : "l"(smem_ptr));
    return addr;
}
__device__ __forceinline__ void ldm_x4(uint32_t r[4], uint32_t addr) {
    asm volatile("ldmatrix.sync.aligned.m8n8.x4.shared.b16 {%0,%1,%2,%3}, [%4];"
        : "=r"(r[0]), "=r"(r[1]), "=r"(r[2]), "=r"(r[3]) : "r"(addr));
}
__device__ __forceinline__ void mma16816(float c[4], const uint32_t a[4],
                                         const uint32_t b0, const uint32_t b1) {
    asm volatile(
        "mma.sync.aligned.m16n8k16.row.col.f32.bf16.bf16.f32 "
        "{%0,%1,%2,%3}, {%4,%5,%6,%7}, {%8,%9}, {%0,%1,%2,%3};"
        : "+f"(c[0]), "+f"(c[1]), "+f"(c[2]), "+f"(c[3])
        : "r"(a[0]), "r"(a[1]), "r"(a[2]), "r"(a[3]), "r"(b0), "r"(b1));
}

// ---------------------------------------------------------------------------
// Kernel A1: raw scaled logits -> g_w[b][n][m]. grid (BSZ, 4), 256 thr.
// (R12 structure: 2-slot unroll per warp, 8 lanes per head.)
// ---------------------------------------------------------------------------
__global__ __launch_bounds__(256) void dnd_logits_kernel(
    const float* __restrict__ keys,   // [T][B][DK]
    const float* __restrict__ rpe,    // [T][B]
    const float* __restrict__ query,  // [B][NH][DK]
    const int*   __restrict__ min_step_p)
{
    __shared__ __align__(16) float sQ[NHEAD * DKDIM];

    const int b    = blockIdx.x;
    const int q    = blockIdx.y;
    const int tid  = threadIdx.x;
    const int warp = tid >> 5;
    const int lane = tid & 31;
    const int M    = min_step_p[0];
    const int ms   = (M * q) >> 2;
    const int me   = (M * (q + 1)) >> 2;

    for (int i = tid; i < NHEAD * DKDIM; i += 256)
        sQ[i] = query[(size_t)b * NHEAD * DKDIM + i];
    __syncthreads();

    const int h = lane >> 3;
    const int j = lane & 7;
    float4 q4[4];
    #pragma unroll
    for (int it = 0; it < 4; ++it)
        q4[it] = ((const float4*)sQ)[h * 32 + it * 8 + j];

    float* __restrict__ wrow = g_w + ((size_t)b * NHEAD + h) * T_MAX;

    const int span = me - ms;
    const int mend2 = ms + (span & ~15);
    for (int m = ms + warp; m < mend2; m += 16) {
        const int m1 = m + 8;
        const float4* __restrict__ ka =
            (const float4*)(keys + ((size_t)m  * BSZ + b) * DKDIM);
        const float4* __restrict__ kb =
            (const float4*)(keys + ((size_t)m1 * BSZ + b) * DKDIM);
        float4 la[4], lb[4];
        #pragma unroll
        for (int it = 0; it < 4; ++it) { la[it] = ldcs4(ka + it * 8 + j); }
        #pragma unroll
        for (int it = 0; it < 4; ++it) { lb[it] = ldcs4(kb + it * 8 + j); }
        float pa = 0.0f, pb = 0.0f;
        #pragma unroll
        for (int it = 0; it < 4; ++it) {
            pa += la[it].x * q4[it].x + la[it].y * q4[it].y
                + la[it].z * q4[it].z + la[it].w * q4[it].w;
            pb += lb[it].x * q4[it].x + lb[it].y * q4[it].y
                + lb[it].z * q4[it].z + lb[it].w * q4[it].w;
        }
        pa += __shfl_down_sync(0xffffffffu, pa, 4);
        pb += __shfl_down_sync(0xffffffffu, pb, 4);
        pa += __shfl_down_sync(0xffffffffu, pa, 2);
        pb += __shfl_down_sync(0xffffffffu, pb, 2);
        pa += __shfl_down_sync(0xffffffffu, pa, 1);
        pb += __shfl_down_sync(0xffffffffu, pb, 1);
        if (j == 0) {
            wrow[m]  = pa * __ldg(&rpe[(size_t)m  * BSZ + b]);
            wrow[m1] = pb * __ldg(&rpe[(size_t)m1 * BSZ + b]);
        }
    }
    for (int m = mend2 + warp; m < me; m += 8) {
        const float4* __restrict__ krow =
            (const float4*)(keys + ((size_t)m * BSZ + b) * DKDIM);
        float p = 0.0f;
        #pragma unroll
        for (int it = 0; it < 4; ++it) {
            const float4 k4 = ldcs4(krow + it * 8 + j);
            p += k4.x * q4[it].x + k4.y * q4[it].y
               + k4.z * q4[it].z + k4.w * q4[it].w;
        }
        p += __shfl_down_sync(0xffffffffu, p, 4);
        p += __shfl_down_sync(0xffffffffu, p, 2);
        p += __shfl_down_sync(0xffffffffu, p, 1);
        if (j == 0)
            wrow[m] = p * __ldg(&rpe[(size_t)m * BSZ + b]);
    }
}

// ---------------------------------------------------------------------------
// Kernel A2: fused softmax + partial res over an m-half.
// grid (BSZ, 2), 128 threads. Stages raw logits, softmaxes them in smem
// (one warp per head, redundantly in both halves), then streams vals.
// ---------------------------------------------------------------------------
__global__ __launch_bounds__(128) void dnd_apply_kernel(
    const float* __restrict__ vals,   // [T][B][VDIM]
    const int*   __restrict__ min_step_p)
{
    __shared__ __align__(16) float sW[NHEAD][T_MAX];

    const int b    = blockIdx.x;
    const int half = blockIdx.y;
    const int tid  = threadIdx.x;
    const int M    = min_step_p[0];
    const int ms   = (M * half) >> 1;
    const int me   = (M * (half + 1)) >> 1;

    // stage raw logits
    {
        const float4* w4 = (const float4*)(g_w + (size_t)b * NHEAD * T_MAX);
        float4* s4 = (float4*)&sW[0][0];
        #pragma unroll
        for (int i = 0; i < 4; ++i)
            s4[tid + 128 * i] = w4[tid + 128 * i];
    }
    __syncthreads();

    // in-smem softmax: one warp per head, row held in 16 registers
    {
        const int warp = tid >> 5;   // head
        const int lane = tid & 31;
        float* row = &sW[warp][0];
        float v[16];
        #pragma unroll
        for (int i = 0; i < 16; ++i) {
            const int m = lane + 32 * i;
            v[i] = (m < M) ? row[m] : -1e30f;
        }
        float mx = -1e30f;
        #pragma unroll
        for (int i = 0; i < 16; ++i) mx = fmaxf(mx, v[i]);
        #pragma unroll
        for (int off = 16; off > 0; off >>= 1)
            mx = fmaxf(mx, __shfl_xor_sync(0xffffffffu, mx, off));
        float s = 0.0f;
        #pragma unroll
        for (int i = 0; i < 16; ++i) {
            v[i] = __expf(v[i] - mx);
            s += v[i];
        }
        #pragma unroll
        for (int off = 16; off > 0; off >>= 1)
            s += __shfl_xor_sync(0xffffffffu, s, off);
        const float inv = 1.0f / s;
        #pragma unroll
        for (int i = 0; i < 16; ++i) {
            const int m = lane + 32 * i;
            if (m < M) row[m] = v[i] * inv;
        }
    }
    __syncthreads();

    float acc[NHEAD][4] = {};
    const float4* __restrict__ V4 = (const float4*)vals;
    const size_t rowstride = (size_t)BSZ * (VDIM / 4);
    const size_t base = (size_t)b * (VDIM / 4) + tid;

    const int span = me - ms;
    const int mend = ms + (span & ~7);
    for (int m0 = ms; m0 < mend; m0 += 8) {
        float4 v[8];
        #pragma unroll
        for (int u = 0; u < 8; ++u)
            v[u] = ldcs4(V4 + base + (size_t)(m0 + u) * rowstride);

        #pragma unroll
        for (int n = 0; n < NHEAD; ++n) {
            const float4 wa = *(const float4*)&sW[n][m0];
            const float4 wb = *(const float4*)&sW[n][m0 + 4];
            acc[n][0] += wa.x * v[0].x; acc[n][1] += wa.x * v[0].y;
            acc[n][2] += wa.x * v[0].z; acc[n][3] += wa.x * v[0].w;
            acc[n][0] += wa.y * v[1].x; acc[n][1] += wa.y * v[1].y;
            acc[n][2] += wa.y * v[1].z; acc[n][3] += wa.y * v[1].w;
            acc[n][0] += wa.z * v[2].x; acc[n][1] += wa.z * v[2].y;
            acc[n][2] += wa.z * v[2].z; acc[n][3] += wa.z * v[2].w;
            acc[n][0] += wa.w * v[3].x; acc[n][1] += wa.w * v[3].y;
            acc[n][2] += wa.w * v[3].z; acc[n][3] += wa.w * v[3].w;
            acc[n][0] += wb.x * v[4].x; acc[n][1] += wb.x * v[4].y;
            acc[n][2] += wb.x * v[4].z; acc[n][3] += wb.x * v[4].w;
            acc[n][0] += wb.y * v[5].x; acc[n][1] += wb.y * v[5].y;
            acc[n][2] += wb.y * v[5].z; acc[n][3] += wb.y * v[5].w;
            acc[n][0] += wb.z * v[6].x; acc[n][1] += wb.z * v[6].y;
            acc[n][2] += wb.z * v[6].z; acc[n][3] += wb.z * v[6].w;
            acc[n][0] += wb.w * v[7].x; acc[n][1] += wb.w * v[7].y;
            acc[n][2] += wb.w * v[7].z; acc[n][3] += wb.w * v[7].w;
        }
    }
    for (int m = mend; m < me; ++m) {
        const float4 v = ldcs4(V4 + base + (size_t)m * rowstride);
        #pragma unroll
        for (int n = 0; n < NHEAD; ++n) {
            const float w = sW[n][m];
            acc[n][0] += w * v.x; acc[n][1] += w * v.y;
            acc[n][2] += w * v.z; acc[n][3] += w * v.w;
        }
    }

    float* __restrict__ rdst = g_res + (size_t)half * BSZ * KIN;
    const int v0 = 4 * tid;
    #pragma unroll
    for (int n = 0; n < NHEAD; ++n) {
        float4 o;
        o.x = acc[n][0]; o.y = acc[n][1]; o.z = acc[n][2]; o.w = acc[n][3];
        *(float4*)&rdst[((size_t)b * NHEAD + n) * VDIM + v0] = o;
    }
}

// ---------------------------------------------------------------------------
// Conversions: fp32 -> bf16 hi/lo (error-compensated split)
// ---------------------------------------------------------------------------
__global__ __launch_bounds__(256) void dnd_conv_res_kernel()
{
    const size_t i = (size_t)blockIdx.x * 256 + threadIdx.x;   // float4 index
    const float4 a = ((const float4*)g_res)[i];
    const float4 b = ((const float4*)(g_res + (size_t)BSZ * KIN))[i];
    float s[4] = {a.x + b.x, a.y + b.y, a.z + b.z, a.w + b.w};
    __nv_bfloat162 h01, h23, l01, l23;
    h01.x = __float2bfloat16(s[0]);
    h01.y = __float2bfloat16(s[1]);
    h23.x = __float2bfloat16(s[2]);
    h23.y = __float2bfloat16(s[3]);
    l01.x = __float2bfloat16(s[0] - __bfloat162float(h01.x));
    l01.y = __float2bfloat16(s[1] - __bfloat162float(h01.y));
    l23.x = __float2bfloat16(s[2] - __bfloat162float(h23.x));
    l23.y = __float2bfloat16(s[3] - __bfloat162float(h23.y));
    ((__nv_bfloat162*)g_res_hi)[2 * i]     = h01;
    ((__nv_bfloat162*)g_res_hi)[2 * i + 1] = h23;
    ((__nv_bfloat162*)g_res_lo)[2 * i]     = l01;
    ((__nv_bfloat162*)g_res_lo)[2 * i + 1] = l23;
}

__global__ __launch_bounds__(256) void dnd_conv_w_kernel(
    const float* __restrict__ W)
{
    const size_t i = (size_t)blockIdx.x * 256 + threadIdx.x;   // float4 index
    const float4 a = ((const float4*)W)[i];
    float s[4] = {a.x, a.y, a.z, a.w};
    __nv_bfloat162 h01, h23, l01, l23;
    h01.x = __float2bfloat16(s[0]);
    h01.y = __float2bfloat16(s[1]);
    h23.x = __float2bfloat16(s[2]);
    h23.y = __float2bfloat16(s[3]);
    l01.x = __float2bfloat16(s[0] - __bfloat162float(h01.x));
    l01.y = __float2bfloat16(s[1] - __bfloat162float(h01.y));
    l23.x = __float2bfloat16(s[2] - __bfloat162float(h23.x));
    l23.y = __float2bfloat16(s[3] - __bfloat162float(h23.y));
    ((__nv_bfloat162*)g_w_hi)[2 * i]     = h01;
    ((__nv_bfloat162*)g_w_hi)[2 * i + 1] = h23;
    ((__nv_bfloat162*)g_w_lo)[2 * i]     = l01;
    ((__nv_bfloat162*)g_w_lo)[2 * i + 1] = l23;
}

// ---------------------------------------------------------------------------
// Kernel B: bf16 mma.sync GEMM with hi/lo compensation (R12 version).
// Tile M=128, N=64, BK=32, 256 threads (8 warps: 4 m x 2 n, warp = 32x32).
// grid (8, 8, KSPLIT) = 256 CTAs. Double-buffered padded smem.
// ---------------------------------------------------------------------------
#define TCM 128
#define TCN 64
#define TCBK 32
#define ASTRIDE 80           // bytes per smem row (32 bf16 + 8 pad)
#define STG 30720            // bytes per stage
#define OFF_AHI 0
#define OFF_ALO 10240
#define OFF_BHI 20480
#define OFF_BLO 25600
#define NSTAGE (KQ / TCBK)   // 16
#define SMEM_DYN (2 * STG)

__global__ __launch_bounds__(256, 1) void dnd_gemm_mma_kernel()
{
    extern __shared__ __align__(16) char smem[];
    const uint32_t sbase = smem_to_u32(smem);

    const int tid  = threadIdx.x;
    const int wid  = tid >> 5;
    const int lane = tid & 31;
    const int bx = blockIdx.x;   // N tile 0..7
    const int by = blockIdx.y;   // M tile 0..7
    const int kz = blockIdx.z;   // 0..KSPLIT-1
    const int wm = wid & 3;      // warp m 0..3 (32 rows each)
    const int wn = wid >> 2;     // warp n 0..1 (32 cols each)

    const size_t arow0 = (size_t)by * TCM;
    const size_t brow0 = (size_t)bx * TCN;
    const size_t kofs  = (size_t)kz * KQ;

    // loader indices: A 512 uint4/array (2 per thread), B 256 (1 per thread)
    const int ar0 = tid >> 2;           // 0..63
    const int aj  = tid & 3;            // uint4 within row
    const uint32_t sA0 = ar0 * ASTRIDE + aj * 16;
    const uint32_t sA1 = (ar0 + 64) * ASTRIDE + aj * 16;
    const uint32_t sB0 = ar0 * ASTRIDE + aj * 16;

    const __nv_bfloat16* gAh0 = g_res_hi + (arow0 + ar0) * KIN + kofs + aj * 8;
    const __nv_bfloat16* gAh1 = gAh0 + (size_t)64 * KIN;
    const __nv_bfloat16* gAl0 = g_res_lo + (arow0 + ar0) * KIN + kofs + aj * 8;
    const __nv_bfloat16* gAl1 = gAl0 + (size_t)64 * KIN;
    const __nv_bfloat16* gBh  = g_w_hi  + (brow0 + ar0) * KIN + kofs + aj * 8;
    const __nv_bfloat16* gBl  = g_w_lo  + (brow0 + ar0) * KIN + kofs + aj * 8;

    // ldmatrix per-lane offsets
    const int aRowOff = ((lane >> 3) & 1) * 8 + (lane & 7);
    const int aKOff   = ((lane >> 4) & 1) * 8;
    const int bNOff   = ((lane >> 4) & 1) * 8 + (lane & 7);
    const int bKOff   = ((lane >> 3) & 1) * 8;

    uint4 pAh0, pAh1, pAl0, pAl1, pBh, pBl;

    // stage 0 load
    pAh0 = *(const uint4*)gAh0;  pAh1 = *(const uint4*)gAh1;
    pAl0 = *(const uint4*)gAl0;  pAl1 = *(const uint4*)gAl1;
    pBh  = *(const uint4*)gBh;   pBl  = *(const uint4*)gBl;
    {
        char* s = smem;
        *(uint4*)(s + OFF_AHI + sA0) = pAh0;
        *(uint4*)(s + OFF_AHI + sA1) = pAh1;
        *(uint4*)(s + OFF_ALO + sA0) = pAl0;
        *(uint4*)(s + OFF_ALO + sA1) = pAl1;
        *(uint4*)(s + OFF_BHI + sB0) = pBh;
        *(uint4*)(s + OFF_BLO + sB0) = pBl;
    }
    __syncthreads();

    float acc[2][4][4] = {};

    for (int st = 0; st < NSTAGE; ++st) {
        const int buf = st & 1;
        const uint32_t bb = sbase + buf * STG;

        if (st + 1 < NSTAGE) {
            const int ke = (st + 1) * TCBK;
            pAh0 = *(const uint4*)(gAh0 + ke);
            pAh1 = *(const uint4*)(gAh1 + ke);
            pAl0 = *(const uint4*)(gAl0 + ke);
            pAl1 = *(const uint4*)(gAl1 + ke);
            pBh  = *(const uint4*)(gBh  + ke);
            pBl  = *(const uint4*)(gBl  + ke);
        }

        #pragma unroll
        for (int ks = 0; ks < TCBK; ks += 16) {
            uint32_t Ah[2][4], Al[2][4], Bh[2][4], Bl[2][4];
            #pragma unroll
            for (int i = 0; i < 2; ++i) {
                const uint32_t arow = (wm * 32 + i * 16 + aRowOff) * ASTRIDE
                                    + (ks + aKOff) * 2;
                ldm_x4(Ah[i], bb + OFF_AHI + arow);
                ldm_x4(Al[i], bb + OFF_ALO + arow);
            }
            #pragma unroll
            for (int t = 0; t < 2; ++t) {
                const uint32_t brow = (wn * 32 + t * 16 + bNOff) * ASTRIDE
                                    + (ks + bKOff) * 2;
                ldm_x4(Bh[t], bb + OFF_BHI + brow);
                ldm_x4(Bl[t], bb + OFF_BLO + brow);
            }
            #pragma unroll
            for (int i = 0; i < 2; ++i) {
                #pragma unroll
                for (int t = 0; t < 2; ++t) {
                    #pragma unroll
                    for (int u = 0; u < 2; ++u) {
                        const int jj = t * 2 + u;
                        mma16816(acc[i][jj], Ah[i], Bh[t][2*u], Bh[t][2*u+1]);
                        mma16816(acc[i][jj], Ah[i], Bl[t][2*u], Bl[t][2*u+1]);
                        mma16816(acc[i][jj], Al[i], Bh[t][2*u], Bh[t][2*u+1]);
                    }
                }
            }
        }

        if (st + 1 < NSTAGE) {
            char* s = smem + ((st + 1) & 1) * STG;
            *(uint4*)(s + OFF_AHI + sA0) = pAh0;
            *(uint4*)(s + OFF_AHI + sA1) = pAh1;
            *(uint4*)(s + OFF_ALO + sA0) = pAl0;
            *(uint4*)(s + OFF_ALO + sA1) = pAl1;
            *(uint4*)(s + OFF_BHI + sB0) = pBh;
            *(uint4*)(s + OFF_BLO + sB0) = pBl;
        }
        __syncthreads();
    }

    // epilogue: c0,c1 at (row, col), c2,c3 at (row+8, col)
    float* __restrict__ part = g_part + (size_t)kz * BSZ * OUTD;
    const int rbase = by * TCM + wm * 32 + (lane >> 2);
    const int cbase = bx * TCN + wn * 32 + 2 * (lane & 3);
    #pragma unroll
    for (int i = 0; i < 2; ++i) {
        #pragma unroll
        for (int jj = 0; jj < 4; ++jj) {
            const int r = rbase + i * 16;
            const int c = cbase + jj * 8;
            float2 o0; o0.x = acc[i][jj][0]; o0.y = acc[i][jj][1];
            float2 o1; o1.x = acc[i][jj][2]; o1.y = acc[i][jj][3];
            *(float2*)(part + (size_t)r * OUTD + c) = o0;
            *(float2*)(part + (size_t)(r + 8) * OUTD + c) = o1;
        }
    }
}

// ---------------------------------------------------------------------------
// Kernel C: out = sum(part[0..KSPLIT-1]) + bias
// ---------------------------------------------------------------------------
__global__ __launch_bounds__(256) void dnd_reduce_kernel(
    const float* __restrict__ bias,
    float* __restrict__ out)
{
    const int i = blockIdx.x * 256 + threadIdx.x;
    const size_t stride4 = (size_t)BSZ * OUTD / 4;
    float4 o = ((const float4*)g_part)[i];
    #pragma unroll
    for (int p = 1; p < KSPLIT; ++p) {
        const float4 a = ((const float4*)g_part)[i + (size_t)p * stride4];
        o.x += a.x; o.y += a.y; o.z += a.z; o.w += a.w;
    }
    const float4 bz = ((const float4*)bias)[i & (OUTD / 4 - 1)];
    o.x += bz.x; o.y += bz.y; o.z += bz.z; o.w += bz.w;
    ((float4*)out)[i] = o;
}

// ---------------------------------------------------------------------------
// Launch
// ---------------------------------------------------------------------------
extern "C" void kernel_launch(void* const* d_in, const int* in_sizes, int n_in,
                              void* d_out, int out_size)
{
    const float* keys  = (const float*)d_in[0];
    const float* vals  = (const float*)d_in[1];
    const float* rpe   = (const float*)d_in[2];
    const float* query = (const float*)d_in[3];
    const float* W     = (const float*)d_in[4];
    const float* bias  = (const float*)d_in[5];
    const int*   mstep = (const int*)d_in[6];

    float* out = (float*)d_out;

    (void)cudaFuncSetAttribute(dnd_gemm_mma_kernel,
        cudaFuncAttributeMaxDynamicSharedMemorySize, SMEM_DYN);

    // W conversion is independent of everything else
    dnd_conv_w_kernel<<<(OUTD * KIN / 4) / 256, 256>>>(W);

    dim3 lgrid(BSZ, 4);
    dnd_logits_kernel<<<lgrid, 256>>>(keys, rpe, query, mstep);

    dim3 agrid(BSZ, 2);
    dnd_apply_kernel<<<agrid, 128>>>(vals, mstep);

    dnd_conv_res_kernel<<<(BSZ * KIN / 4) / 256, 256>>>();

    dim3 ggrid(OUTD / TCN, BSZ / TCM, KSPLIT);   // (8, 8, 4)
    dnd_gemm_mma_kernel<<<ggrid, 256, SMEM_DYN>>>();

    dnd_reduce_kernel<<<(BSZ * OUTD / 4) / 256, 256>>>(bias, out);
}